// round 10
// baseline (speedup 1.0000x reference)
#include <cuda_runtime.h>
#include <cuda_fp16.h>
#include <cstdint>

// y[n,k] = log( sum_l clip(mu[n,l],EPS) * softmax(leaf_scores[l,:])[k] )
// N=32768, L=256, C=64.
// S = fp16(mu_hat) @ fp16(Q) via mma.sync m16n8k16, fp32 accumulate, then log.
// Error: independent ~2^-11/2^-12 roundings on A and B terms -> norm rel_err
// ~5-9e-5 (measured 3.7e-5 with B-only rounding), >10x inside the 1e-3 budget.

#define LL 256
#define CC 64
#define EPSV 1e-12f
#define TPB 128
#define BN  64
#define BROWH 544   // bytes per B class-row: 256 fp16 (512B) + 32 pad
                    // (stride%128==32 -> each 16-lane LDS.64 phase bank-clean)

// B: per class row, leaf group j (4 leaves) at byte j*8: [x4 fp16].
__device__ __align__(16) char g_B[CC * BROWH];

// ---------------- Kernel 1: softmax -> fp16 Q (one leaf per warp) ----------
__global__ void softmax_kernel(const float* __restrict__ s) {
    const int l = blockIdx.x * 8 + (threadIdx.x >> 5);
    const int t = threadIdx.x & 31;
    const float a = s[l * CC + t];
    const float b = s[l * CC + t + 32];
    float m = fmaxf(a, b);
    #pragma unroll
    for (int off = 16; off > 0; off >>= 1)
        m = fmaxf(m, __shfl_xor_sync(0xFFFFFFFFu, m, off));
    const float ea = expf(a - m);
    const float eb = expf(b - m);
    float sum = ea + eb;
    #pragma unroll
    for (int off = 16; off > 0; off >>= 1)
        sum += __shfl_xor_sync(0xFFFFFFFFu, sum, off);
    const float inv = 1.0f / sum;

    const int grp = (l >> 2) * 8 + (l & 3) * 2;   // byte offset within class row
    *(__half*)(g_B + t * BROWH + grp)        = __float2half_rn(ea * inv);
    *(__half*)(g_B + (t + 32) * BROWH + grp) = __float2half_rn(eb * inv);
}

// ---------------- helpers ----------------
__device__ __forceinline__ void mma_f16(float* d,
    uint32_t a0, uint32_t a1, uint32_t a2, uint32_t a3, uint32_t b0, uint32_t b1)
{
    asm volatile("mma.sync.aligned.m16n8k16.row.col.f32.f16.f16.f32 "
                 "{%0,%1,%2,%3}, {%4,%5,%6,%7}, {%8,%9}, {%0,%1,%2,%3};"
                 : "+f"(d[0]), "+f"(d[1]), "+f"(d[2]), "+f"(d[3])
                 : "r"(a0), "r"(a1), "r"(a2), "r"(a3), "r"(b0), "r"(b1));
}

// clamp + pack float4 -> two fp16x2 fragments (e0,e1)(e2,e3)
__device__ __forceinline__ void pack4(float4 f, uint32_t& h01, uint32_t& h23) {
    f.x = fmaxf(f.x, EPSV); f.y = fmaxf(f.y, EPSV);
    f.z = fmaxf(f.z, EPSV); f.w = fmaxf(f.w, EPSV);
    __half2 h0 = __float22half2_rn(make_float2(f.x, f.y));
    __half2 h1 = __float22half2_rn(make_float2(f.z, f.w));
    h01 = *reinterpret_cast<uint32_t*>(&h0);
    h23 = *reinterpret_cast<uint32_t*>(&h1);
}

// ---------------- Kernel 2: HMMA mixture GEMM + log ----------------
extern __shared__ char sB[];   // [CC * BROWH] = 34816 bytes

__global__ void __launch_bounds__(TPB, 5) leafmix_kernel(
    const float* __restrict__ mu, float* __restrict__ out)
{
    // stage B into smem, coalesced uint4: 2176 / 128 = 17 iters exact
    {
        const uint4* gq = (const uint4*)g_B;
        uint4* sq = (uint4*)sB;
        #pragma unroll
        for (int j = 0; j < 17; j++)
            sq[threadIdx.x + j * TPB] = gq[threadIdx.x + j * TPB];
    }
    __syncthreads();

    const int tid = threadIdx.x;
    const int w = tid >> 5;
    const int lane = tid & 31;
    const int g = lane >> 2;   // row-group / B-column index
    const int r = lane & 3;    // k quad

    const int rb = blockIdx.x * BN + w * 16 + g;
    const float* A0 = mu + (size_t)rb * LL + r * 4;   // row g
    const float* A1 = A0 + 8 * LL;                    // row g+8

    const char* Bp = sB + g * BROWH + r * 8;

    float acc[8][4];
    #pragma unroll
    for (int nt = 0; nt < 8; nt++)
        #pragma unroll
        for (int q = 0; q < 4; q++) acc[nt][q] = 0.0f;

    // ---- A register ring, prefetch distance 2 ----
    float4 fa[2], fb[2];
    #pragma unroll
    for (int p = 0; p < 2; p++) {
        fa[p] = *(const float4*)(A0 + p * 16);
        fb[p] = *(const float4*)(A1 + p * 16);
    }

    #pragma unroll
    for (int kk = 0; kk < 16; kk++) {
        const int p = kk & 1;

        uint32_t ah0, ah2;   // row g:   (e0,e1),(e2,e3)
        uint32_t ah1, ah3;   // row g+8
        pack4(fa[p], ah0, ah2);
        pack4(fb[p], ah1, ah3);

        if (kk + 2 < 16) {
            fa[p] = *(const float4*)(A0 + (kk + 2) * 16);
            fb[p] = *(const float4*)(A1 + (kk + 2) * 16);
        }

        const char* bk = Bp + kk * 32;
        #pragma unroll
        for (int nt = 0; nt < 8; nt++) {
            const uint2 q = *(const uint2*)(bk + nt * 8 * BROWH);
            mma_f16(acc[nt], ah0, ah1, ah2, ah3, q.x, q.y);
        }
    }

    // ---- epilogue: log + store ----
    float* o0 = out + (size_t)rb * CC + r * 2;
    float* o1 = o0 + 8 * CC;
    #pragma unroll
    for (int nt = 0; nt < 8; nt++) {
        *(float2*)(o0 + nt * 8) = make_float2(__logf(acc[nt][0]), __logf(acc[nt][1]));
        *(float2*)(o1 + nt * 8) = make_float2(__logf(acc[nt][2]), __logf(acc[nt][3]));
    }
}

extern "C" void kernel_launch(void* const* d_in, const int* in_sizes, int n_in,
                              void* d_out, int out_size) {
    const float* mu = (const float*)d_in[0];           // (N, L) fp32
    const float* leaf_scores = (const float*)d_in[1];  // (L, C) fp32
    float* out = (float*)d_out;                        // (N, C) fp32

    const int N = in_sizes[0] / LL;
    const int smem_bytes = CC * BROWH;   // 34816

    static bool attr_set = false;
    if (!attr_set) {
        cudaFuncSetAttribute(leafmix_kernel,
                             cudaFuncAttributeMaxDynamicSharedMemorySize, smem_bytes);
        attr_set = true;
    }

    softmax_kernel<<<LL / 8, 256>>>(leaf_scores);
    leafmix_kernel<<<N / BN, TPB, smem_bytes>>>(mu, out);
}